// round 8
// baseline (speedup 1.0000x reference)
#include <cuda_runtime.h>
#include <math.h>

#define MAX_N 1024
#define EPS   1e-4f

// ---- scratch (__device__ globals; no allocation allowed) ----
__device__ float g_diag[MAX_N * 64];    // per-node sum of R^T R
__device__ float g_dis [MAX_N * 64];    // per-node D^{-1/2}

// ---- per-edge FtF = R^T R, atomically accumulated into g_diag[i] ----
__global__ void k_ftf(const float* __restrict__ R, const int* __restrict__ E, int P) {
    int gid = blockIdx.x * blockDim.x + threadIdx.x;
    if (gid >= P * 64) return;
    int p = gid >> 6;
    int e = gid & 63;
    int r = e >> 3, c = e & 7;
    int i = E[2 * p];
    const float* Rp = R + (size_t)p * 64;
    float v = 0.f;
#pragma unroll
    for (int k = 0; k < 8; k++) v += Rp[k * 8 + r] * Rp[k * 8 + c];
    atomicAdd(&g_diag[i * 64 + e], v);
}

// ---- per-node D^{-1/2} via coupled Newton-Schulz (SPD, lambda >= EPS) ----
__global__ void k_ns(int n) {
    __shared__ float Y[64], Z[64], G[64], red[64];
    int v = blockIdx.x;
    int t = threadIdx.x;
    int r = t >> 3, c = t & 7;

    float a = g_diag[v * 64 + r * 8 + c];
    float b = g_diag[v * 64 + c * 8 + r];
    float d = 0.5f * (a + b) + ((r == c) ? EPS : 0.f);

    red[t] = d * d;
    __syncthreads();
    if (t < 32) red[t] += red[t + 32];
    __syncthreads();
    if (t < 32) {
        float s = red[t];
#pragma unroll
        for (int o = 16; o > 0; o >>= 1) s += __shfl_down_sync(0xffffffffu, s, o);
        if (t == 0) red[0] = s;
    }
    __syncthreads();
    float s = sqrtf(red[0]);
    float inv_s = 1.f / s;

    Y[t] = d * inv_s;
    Z[t] = (r == c) ? 1.f : 0.f;
    __syncthreads();

    for (int it = 0; it < 24; it++) {
        float acc = 0.f;
#pragma unroll
        for (int k = 0; k < 8; k++) acc += Z[r * 8 + k] * Y[k * 8 + c];
        float g = ((r == c) ? 1.5f : 0.f) - 0.5f * acc;
        __syncthreads();
        G[t] = g;
        __syncthreads();
        float ny = 0.f, nz = 0.f;
#pragma unroll
        for (int k = 0; k < 8; k++) {
            ny += Y[r * 8 + k] * G[k * 8 + c];
            nz += G[r * 8 + k] * Z[k * 8 + c];
        }
        __syncthreads();
        Y[t] = ny;
        Z[t] = nz;
        __syncthreads();
    }

    g_dis[v * 64 + t] = Z[t] * rsqrtf(s);
}

// ---- k_blocks v2: 256 threads/CTA, 4 output blocks per CTA.
//      M1 stored TRANSPOSED so every matmul stage reads its left operand
//      contiguously (2x LDS.128) and right operand stride-8 scalar.
//      reverse edge of p is (p +- P/2) by construction (directed = [fwd; bwd]) ----
__global__ void k_blocks(const float* __restrict__ R, const int* __restrict__ E,
                         const float* __restrict__ L1, float* __restrict__ out,
                         int P, int n) {
    __shared__ float M1T[4][64], M2[4][64], Di[4][64], Dj[4][64], B[4][64], T[4][64];
    int sub = threadIdx.x >> 6;          // 0..3: which output block
    int t   = threadIdx.x & 63;          // 0..63 within block
    int b   = blockIdx.x * 4 + sub;
    bool valid = (b < P + n);
    bool is_edge = valid && (b < P);
    int i = 0, j = 0;
    float sgn = 0.f;

    if (valid) {
        if (is_edge) {
            int2 e = ((const int2*)E)[b];
            i = e.x; j = e.y;
        } else {
            i = j = b - P;
        }
    }

    int r = t >> 3, c = t & 7;
    int g = t & 15, sel = t >> 4;        // cooperative float4 loads (16 thr/operand)

    if (valid) {
        if (is_edge) {
            int half = P >> 1;
            int rev = (b < half) ? (b + half) : (b - half);
            float l = L1[(size_t)i * n + j];
            sgn = (l > 0.f) ? 1.f : ((l < 0.f) ? -1.f : 0.f);
            if (sel == 0) {
                // load row (g>>1) cols (g&1)*4.. of R_ji, store TRANSPOSED
                float4 v = ((const float4*)(R + (size_t)rev * 64))[g];
                int row = g >> 1, c0 = (g & 1) * 4;
                M1T[sub][(c0 + 0) * 8 + row] = v.x;
                M1T[sub][(c0 + 1) * 8 + row] = v.y;
                M1T[sub][(c0 + 2) * 8 + row] = v.z;
                M1T[sub][(c0 + 3) * 8 + row] = v.w;
            } else if (sel == 1) {
                ((float4*)M2[sub])[g] = ((const float4*)(R + (size_t)b * 64))[g];
            } else if (sel == 2) {
                ((float4*)Di[sub])[g] = ((const float4*)(g_dis + (size_t)i * 64))[g];
            } else {
                ((float4*)Dj[sub])[g] = ((const float4*)(g_dis + (size_t)j * 64))[g];
            }
        } else {
            if (sel == 0) {
                ((float4*)B[sub])[g]  = ((const float4*)(g_diag + (size_t)i * 64))[g];
            } else if (sel == 2) {
                ((float4*)Di[sub])[g] = ((const float4*)(g_dis + (size_t)i * 64))[g];
            } else if (sel == 3) {
                ((float4*)Dj[sub])[g] = ((const float4*)(g_dis + (size_t)i * 64))[g];
            }
        }
    }
    __syncthreads();

    if (is_edge) {
        // B[r][c] = -sgn * sum_k R_ji[k][r] * R_ij[k][c]
        //         = -sgn * sum_k M1T[r*8+k] * M2[k*8+c]
        float4 a0 = ((const float4*)(M1T[sub] + r * 8))[0];
        float4 a1 = ((const float4*)(M1T[sub] + r * 8))[1];
        const float* Bc = M2[sub] + c;
        float s = a0.x * Bc[0]  + a0.y * Bc[8]  + a0.z * Bc[16] + a0.w * Bc[24]
                + a1.x * Bc[32] + a1.y * Bc[40] + a1.z * Bc[48] + a1.w * Bc[56];
        B[sub][t] = -sgn * s;
    }
    __syncthreads();
    if (valid) {
        // T = Di @ B
        float4 a0 = ((const float4*)(Di[sub] + r * 8))[0];
        float4 a1 = ((const float4*)(Di[sub] + r * 8))[1];
        const float* Bc = B[sub] + c;
        float s = a0.x * Bc[0]  + a0.y * Bc[8]  + a0.z * Bc[16] + a0.w * Bc[24]
                + a1.x * Bc[32] + a1.y * Bc[40] + a1.z * Bc[48] + a1.w * Bc[56];
        T[sub][t] = s;
    }
    __syncthreads();
    if (valid) {
        // out_block = T @ Dj
        float4 a0 = ((const float4*)(T[sub] + r * 8))[0];
        float4 a1 = ((const float4*)(T[sub] + r * 8))[1];
        const float* Bc = Dj[sub] + c;
        float s = a0.x * Bc[0]  + a0.y * Bc[8]  + a0.z * Bc[16] + a0.w * Bc[24]
                + a1.x * Bc[32] + a1.y * Bc[40] + a1.z * Bc[48] + a1.w * Bc[56];
        size_t nd = (size_t)n * 8;
        out[((size_t)i * 8 + r) * nd + (size_t)j * 8 + c] = s;
    }
}

extern "C" void kernel_launch(void* const* d_in, const int* in_sizes, int n_in,
                              void* d_out, int out_size) {
    const float* R  = (const float*)d_in[0];  // (P, 8, 8)
    const int*   E  = (const int*)  d_in[1];  // (P, 2)
    const float* L1 = (const float*)d_in[3];  // (n, n)

    int P = in_sizes[1] / 2;
    int n = (int)(sqrt((double)in_sizes[3]) + 0.5);

    // one-time host-side resources (streams/events are NOT device memory)
    static bool inited = false;
    static cudaStream_t side;
    static cudaEvent_t ev_fork, ev_chain;
    static void* diag_ptr;
    if (!inited) {
        cudaStreamCreateWithFlags(&side, cudaStreamNonBlocking);
        cudaEventCreateWithFlags(&ev_fork, cudaEventDisableTiming);
        cudaEventCreateWithFlags(&ev_chain, cudaEventDisableTiming);
        cudaGetSymbolAddress(&diag_ptr, g_diag);
        inited = true;
    }

    // fork side stream at t=0: compute chain (independent of d_out)
    cudaEventRecord(ev_fork, 0);
    cudaStreamWaitEvent(side, ev_fork, 0);
    cudaMemsetAsync(diag_ptr, 0, (size_t)n * 64 * sizeof(float), side);
    k_ftf<<<(P * 64 + 255) / 256, 256, 0, side>>>(R, E, P);
    k_ns<<<n, 64, 0, side>>>(n);
    cudaEventRecord(ev_chain, side);

    // main stream: full-buffer driver memset (the fast zero path, ~45us)
    cudaMemsetAsync(d_out, 0, (size_t)out_size * sizeof(float), 0);

    // tail: nonzero-block writer, after both memset and chain
    cudaStreamWaitEvent(0, ev_chain, 0);
    int nblk = P + n;
    k_blocks<<<(nblk + 3) / 4, 256>>>(R, E, L1, (float*)d_out, P, n);
}

// round 9
// speedup vs baseline: 1.2520x; 1.2520x over previous
#include <cuda_runtime.h>
#include <math.h>
#include <stdint.h>

#define MAX_N 1024
#define EPS   1e-4f
#define ZCHUNK 32768          // bytes per bulk store
#define ZPER   4              // chunks per CTA

// ---- scratch (__device__ globals; no allocation allowed) ----
__device__ float g_diag[MAX_N * 64];    // per-node sum of R^T R
__device__ float g_dis [MAX_N * 64];    // per-node D^{-1/2}

// ---- zero the whole output via TMA bulk stores (bypasses STG issue limit) ----
__global__ void k_zero_tma(char* __restrict__ out, size_t total) {
    __shared__ __align__(128) char buf[ZCHUNK];
    float4* b4 = (float4*)buf;
    for (int t = threadIdx.x; t < ZCHUNK / 16; t += blockDim.x)
        b4[t] = make_float4(0.f, 0.f, 0.f, 0.f);
    __syncthreads();
    asm volatile("fence.proxy.async.shared::cta;" ::: "memory");
    if (threadIdx.x == 0) {
        uint32_t saddr;
        asm("{ .reg .u64 t; cvta.to.shared.u64 t, %1; cvt.u32.u64 %0, t; }"
            : "=r"(saddr) : "l"(buf));
        size_t base = (size_t)blockIdx.x * (ZPER * (size_t)ZCHUNK);
#pragma unroll
        for (int k = 0; k < ZPER; k++) {
            size_t off = base + (size_t)k * ZCHUNK;
            if (off >= total) break;
            size_t rem = total - off;
            unsigned len = (unsigned)(rem >= ZCHUNK ? ZCHUNK : rem);
            asm volatile(
                "cp.async.bulk.global.shared::cta.bulk_group [%0], [%1], %2;"
                :: "l"(out + off), "r"(saddr), "r"(len) : "memory");
        }
        asm volatile("cp.async.bulk.commit_group;" ::: "memory");
        asm volatile("cp.async.bulk.wait_group 0;" ::: "memory");
    }
}

// ---- per-edge FtF = R^T R, atomically accumulated into g_diag[i] ----
__global__ void k_ftf(const float* __restrict__ R, const int* __restrict__ E, int P) {
    int gid = blockIdx.x * blockDim.x + threadIdx.x;
    if (gid >= P * 64) return;
    int p = gid >> 6;
    int e = gid & 63;
    int r = e >> 3, c = e & 7;
    int i = E[2 * p];
    const float* Rp = R + (size_t)p * 64;
    float v = 0.f;
#pragma unroll
    for (int k = 0; k < 8; k++) v += Rp[k * 8 + r] * Rp[k * 8 + c];
    atomicAdd(&g_diag[i * 64 + e], v);
}

// ---- per-node D^{-1/2} via coupled Newton-Schulz (SPD, lambda >= EPS) ----
__global__ void k_ns(int n) {
    __shared__ float Y[64], Z[64], G[64], red[64];
    int v = blockIdx.x;
    int t = threadIdx.x;
    int r = t >> 3, c = t & 7;

    float a = g_diag[v * 64 + r * 8 + c];
    float b = g_diag[v * 64 + c * 8 + r];
    float d = 0.5f * (a + b) + ((r == c) ? EPS : 0.f);

    red[t] = d * d;
    __syncthreads();
    if (t < 32) red[t] += red[t + 32];
    __syncthreads();
    if (t < 32) {
        float s = red[t];
#pragma unroll
        for (int o = 16; o > 0; o >>= 1) s += __shfl_down_sync(0xffffffffu, s, o);
        if (t == 0) red[0] = s;
    }
    __syncthreads();
    float s = sqrtf(red[0]);
    float inv_s = 1.f / s;

    Y[t] = d * inv_s;
    Z[t] = (r == c) ? 1.f : 0.f;
    __syncthreads();

    for (int it = 0; it < 24; it++) {
        float acc = 0.f;
#pragma unroll
        for (int k = 0; k < 8; k++) acc += Z[r * 8 + k] * Y[k * 8 + c];
        float g = ((r == c) ? 1.5f : 0.f) - 0.5f * acc;
        __syncthreads();
        G[t] = g;
        __syncthreads();
        float ny = 0.f, nz = 0.f;
#pragma unroll
        for (int k = 0; k < 8; k++) {
            ny += Y[r * 8 + k] * G[k * 8 + c];
            nz += G[r * 8 + k] * Z[k * 8 + c];
        }
        __syncthreads();
        Y[t] = ny;
        Z[t] = nz;
        __syncthreads();
    }

    g_dis[v * 64 + t] = Z[t] * rsqrtf(s);
}

// ---- k_blocks v2: 256 threads/CTA, 4 output blocks per CTA.
//      M1 stored TRANSPOSED so every matmul stage reads its left operand
//      contiguously (2x LDS.128); reverse edge of p is (p +- P/2). ----
__global__ void k_blocks(const float* __restrict__ R, const int* __restrict__ E,
                         const float* __restrict__ L1, float* __restrict__ out,
                         int P, int n) {
    __shared__ float M1T[4][64], M2[4][64], Di[4][64], Dj[4][64], B[4][64], T[4][64];
    int sub = threadIdx.x >> 6;          // 0..3: which output block
    int t   = threadIdx.x & 63;          // 0..63 within block
    int b   = blockIdx.x * 4 + sub;
    bool valid = (b < P + n);
    bool is_edge = valid && (b < P);
    int i = 0, j = 0;
    float sgn = 0.f;

    if (valid) {
        if (is_edge) {
            int2 e = ((const int2*)E)[b];
            i = e.x; j = e.y;
        } else {
            i = j = b - P;
        }
    }

    int r = t >> 3, c = t & 7;
    int g = t & 15, sel = t >> 4;        // cooperative float4 loads (16 thr/operand)

    if (valid) {
        if (is_edge) {
            int half = P >> 1;
            int rev = (b < half) ? (b + half) : (b - half);
            float l = L1[(size_t)i * n + j];
            sgn = (l > 0.f) ? 1.f : ((l < 0.f) ? -1.f : 0.f);
            if (sel == 0) {
                float4 v = ((const float4*)(R + (size_t)rev * 64))[g];
                int row = g >> 1, c0 = (g & 1) * 4;
                M1T[sub][(c0 + 0) * 8 + row] = v.x;
                M1T[sub][(c0 + 1) * 8 + row] = v.y;
                M1T[sub][(c0 + 2) * 8 + row] = v.z;
                M1T[sub][(c0 + 3) * 8 + row] = v.w;
            } else if (sel == 1) {
                ((float4*)M2[sub])[g] = ((const float4*)(R + (size_t)b * 64))[g];
            } else if (sel == 2) {
                ((float4*)Di[sub])[g] = ((const float4*)(g_dis + (size_t)i * 64))[g];
            } else {
                ((float4*)Dj[sub])[g] = ((const float4*)(g_dis + (size_t)j * 64))[g];
            }
        } else {
            if (sel == 0) {
                ((float4*)B[sub])[g]  = ((const float4*)(g_diag + (size_t)i * 64))[g];
            } else if (sel == 2) {
                ((float4*)Di[sub])[g] = ((const float4*)(g_dis + (size_t)i * 64))[g];
            } else if (sel == 3) {
                ((float4*)Dj[sub])[g] = ((const float4*)(g_dis + (size_t)i * 64))[g];
            }
        }
    }
    __syncthreads();

    if (is_edge) {
        float4 a0 = ((const float4*)(M1T[sub] + r * 8))[0];
        float4 a1 = ((const float4*)(M1T[sub] + r * 8))[1];
        const float* Bc = M2[sub] + c;
        float s = a0.x * Bc[0]  + a0.y * Bc[8]  + a0.z * Bc[16] + a0.w * Bc[24]
                + a1.x * Bc[32] + a1.y * Bc[40] + a1.z * Bc[48] + a1.w * Bc[56];
        B[sub][t] = -sgn * s;
    }
    __syncthreads();
    if (valid) {
        float4 a0 = ((const float4*)(Di[sub] + r * 8))[0];
        float4 a1 = ((const float4*)(Di[sub] + r * 8))[1];
        const float* Bc = B[sub] + c;
        float s = a0.x * Bc[0]  + a0.y * Bc[8]  + a0.z * Bc[16] + a0.w * Bc[24]
                + a1.x * Bc[32] + a1.y * Bc[40] + a1.z * Bc[48] + a1.w * Bc[56];
        T[sub][t] = s;
    }
    __syncthreads();
    if (valid) {
        float4 a0 = ((const float4*)(T[sub] + r * 8))[0];
        float4 a1 = ((const float4*)(T[sub] + r * 8))[1];
        const float* Bc = Dj[sub] + c;
        float s = a0.x * Bc[0]  + a0.y * Bc[8]  + a0.z * Bc[16] + a0.w * Bc[24]
                + a1.x * Bc[32] + a1.y * Bc[40] + a1.z * Bc[48] + a1.w * Bc[56];
        size_t nd = (size_t)n * 8;
        out[((size_t)i * 8 + r) * nd + (size_t)j * 8 + c] = s;
    }
}

extern "C" void kernel_launch(void* const* d_in, const int* in_sizes, int n_in,
                              void* d_out, int out_size) {
    const float* R  = (const float*)d_in[0];  // (P, 8, 8)
    const int*   E  = (const int*)  d_in[1];  // (P, 2)
    const float* L1 = (const float*)d_in[3];  // (n, n)

    int P = in_sizes[1] / 2;
    int n = (int)(sqrt((double)in_sizes[3]) + 0.5);

    // one-time host-side resources (streams/events are NOT device memory)
    static bool inited = false;
    static cudaStream_t side;
    static cudaEvent_t ev_fork, ev_chain;
    static void* diag_ptr;
    if (!inited) {
        cudaStreamCreateWithFlags(&side, cudaStreamNonBlocking);
        cudaEventCreateWithFlags(&ev_fork, cudaEventDisableTiming);
        cudaEventCreateWithFlags(&ev_chain, cudaEventDisableTiming);
        cudaGetSymbolAddress(&diag_ptr, g_diag);
        inited = true;
    }

    // fork side stream at t=0: compute chain (independent of d_out)
    cudaEventRecord(ev_fork, 0);
    cudaStreamWaitEvent(side, ev_fork, 0);
    cudaMemsetAsync(diag_ptr, 0, (size_t)n * 64 * sizeof(float), side);
    k_ftf<<<(P * 64 + 255) / 256, 256, 0, side>>>(R, E, P);
    k_ns<<<n, 64, 0, side>>>(n);
    cudaEventRecord(ev_chain, side);

    // main stream: TMA bulk-store zero of the whole output
    size_t total = (size_t)out_size * sizeof(float);
    size_t per_cta = (size_t)ZPER * ZCHUNK;
    int zgrid = (int)((total + per_cta - 1) / per_cta);
    k_zero_tma<<<zgrid, 128>>>((char*)d_out, total);

    // tail: nonzero-block writer, after both zero and chain
    cudaStreamWaitEvent(0, ev_chain, 0);
    int nblk = P + n;
    k_blocks<<<(nblk + 3) / 4, 256>>>(R, E, L1, (float*)d_out, P, n);
}